// round 2
// baseline (speedup 1.0000x reference)
#include <cuda_runtime.h>
#include <math.h>

#define HD 512
#define NLAYER 3
#define BATCH 16384
#define FF 2048   // 4*HD

// ---------------- device scratch (no allocations allowed) ----------------
__device__ float g_Watt[6 * HD * HD];                    // folded ao_w @ wv, [i*3+l][m][k]
__device__ float g_batt[6 * HD];                         // folded bias
__device__ float g_ATT[(size_t)2 * BATCH * 3 * HD];      // per-gen, per-layer attention adds
__device__ float g_X[(size_t)BATCH * HD];                // running activation
__device__ float g_Hbuf[(size_t)BATCH * FF];             // FFN hidden
__device__ float g_T[(size_t)BATCH * HD];                // FFN output temp
__device__ float g_gen0[(size_t)BATCH * HD];             // gen_text
__device__ float g_gen1[(size_t)BATCH * HD];             // gen_img
__device__ float g_prior[2 * HD];                        // prior MLP output (batch-invariant)

// ---------------- helpers ----------------
__device__ __forceinline__ unsigned f2tf(float f) {
    unsigned u;
    asm("cvt.rna.tf32.f32 %0, %1;" : "=r"(u) : "f"(f));
    return u;
}

__device__ __forceinline__ float gelu_f(float x) {
    // exact gelu (approximate=False): 0.5*x*(1+erf(x/sqrt(2)))
    return 0.5f * x * (1.0f + erff(x * 0.70710678118654752f));
}

__device__ __forceinline__ void mma_tf32(float c[4], const unsigned a[4], const unsigned b[2]) {
    asm volatile(
        "mma.sync.aligned.m16n8k8.row.col.f32.tf32.tf32.f32 "
        "{%0,%1,%2,%3},{%4,%5,%6,%7},{%8,%9},{%0,%1,%2,%3};\n"
        : "+f"(c[0]), "+f"(c[1]), "+f"(c[2]), "+f"(c[3])
        : "r"(a[0]), "r"(a[1]), "r"(a[2]), "r"(a[3]), "r"(b[0]), "r"(b[1]));
}

// ---------------- GEMM ----------------
// C[m,n] = sum_k A[m,k] * B'[k,n] + bias[n]    (optional GELU)
// TRANSB=1: B' = W^T with W row-major [N,K]  (the x @ W.T case)
// TRANSB=0: B' = W   with W row-major [K,N]  (plain matmul, used for weight folding)
// Requires: M%128==0, N%128==0, K%16==0. No bounds checks.
// Double-buffered smem; tf32 conversion done once at staging time.
template <bool TRANSB, bool GELU>
__global__ void __launch_bounds__(256) gemm_kernel(
    const float* __restrict__ A, const float* __restrict__ W,
    const float* __restrict__ bias, float* __restrict__ C,
    int M, int N, int K)
{
    constexpr int BM = 128, BN = 128, BK = 16;
    __shared__ unsigned As[2][BM][20];    // pad 16->20: conflict-free A fragment LDS
    __shared__ unsigned Bs[2][BK][136];   // pad 128->136: conflict-free B fragment LDS

    const int t    = threadIdx.x;
    const int lane = t & 31;
    const int warp = t >> 5;
    const int wm   = warp >> 2;   // 0..1  (warp grid 2 x 4)
    const int wn   = warp & 3;    // 0..3
    const int gq   = lane >> 2;   // groupID 0..7
    const int tg   = lane & 3;    // threadID_in_group 0..3

    const int bm = blockIdx.y * BM;
    const int bn = blockIdx.x * BN;

    float acc[4][4][4];
#pragma unroll
    for (int a = 0; a < 4; a++)
#pragma unroll
        for (int b = 0; b < 4; b++)
#pragma unroll
            for (int c = 0; c < 4; c++) acc[a][b][c] = 0.0f;

    // A staging: 128x16 tile, 2 float4 per thread
    const int ar  = t >> 2;   // 0..63
    const int ac4 = t & 3;    // 0..3
    const float* Abase = A + (size_t)(bm + ar) * K + ac4 * 4;

    float4 ra0, ra1, rb0, rb1;

    auto loadAB = [&](int kt) {
        const float* ap = Abase + kt * BK;
        ra0 = *(const float4*)(ap);
        ra1 = *(const float4*)(ap + (size_t)64 * K);
        if constexpr (TRANSB) {
            const int n  = t & 127;
            const int c4 = t >> 7;   // 0 or 1; second load uses c4+2
            const float* bp = W + (size_t)(bn + n) * K + kt * BK;
            rb0 = *(const float4*)(bp + c4 * 4);
            rb1 = *(const float4*)(bp + (c4 + 2) * 4);
        } else {
            const int k0 = t >> 5;   // 0..7; second load row k0+8
            const int c4 = t & 31;
            const float* bp = W + (size_t)(kt * BK + k0) * N + bn + c4 * 4;
            rb0 = *(const float4*)(bp);
            rb1 = *(const float4*)(bp + (size_t)8 * N);
        }
    };
    auto storeAB = [&](int buf) {
        // convert to tf32 bit pattern ONCE here (inner loop does raw LDS only)
        As[buf][ar][ac4 * 4 + 0]      = f2tf(ra0.x);
        As[buf][ar][ac4 * 4 + 1]      = f2tf(ra0.y);
        As[buf][ar][ac4 * 4 + 2]      = f2tf(ra0.z);
        As[buf][ar][ac4 * 4 + 3]      = f2tf(ra0.w);
        As[buf][ar + 64][ac4 * 4 + 0] = f2tf(ra1.x);
        As[buf][ar + 64][ac4 * 4 + 1] = f2tf(ra1.y);
        As[buf][ar + 64][ac4 * 4 + 2] = f2tf(ra1.z);
        As[buf][ar + 64][ac4 * 4 + 3] = f2tf(ra1.w);
        if constexpr (TRANSB) {
            const int n  = t & 127;
            const int c4 = t >> 7;
            Bs[buf][c4 * 4 + 0][n] = f2tf(rb0.x);
            Bs[buf][c4 * 4 + 1][n] = f2tf(rb0.y);
            Bs[buf][c4 * 4 + 2][n] = f2tf(rb0.z);
            Bs[buf][c4 * 4 + 3][n] = f2tf(rb0.w);
            const int c4b = c4 + 2;
            Bs[buf][c4b * 4 + 0][n] = f2tf(rb1.x);
            Bs[buf][c4b * 4 + 1][n] = f2tf(rb1.y);
            Bs[buf][c4b * 4 + 2][n] = f2tf(rb1.z);
            Bs[buf][c4b * 4 + 3][n] = f2tf(rb1.w);
        } else {
            const int k0 = t >> 5;
            const int c4 = t & 31;
            Bs[buf][k0][c4 * 4 + 0]     = f2tf(rb0.x);
            Bs[buf][k0][c4 * 4 + 1]     = f2tf(rb0.y);
            Bs[buf][k0][c4 * 4 + 2]     = f2tf(rb0.z);
            Bs[buf][k0][c4 * 4 + 3]     = f2tf(rb0.w);
            Bs[buf][k0 + 8][c4 * 4 + 0] = f2tf(rb1.x);
            Bs[buf][k0 + 8][c4 * 4 + 1] = f2tf(rb1.y);
            Bs[buf][k0 + 8][c4 * 4 + 2] = f2tf(rb1.z);
            Bs[buf][k0 + 8][c4 * 4 + 3] = f2tf(rb1.w);
        }
    };

    const int KT = K / BK;
    loadAB(0);
    storeAB(0);
    __syncthreads();

    for (int kt = 0; kt < KT; ++kt) {
        const int buf = kt & 1;
        const bool more = (kt + 1 < KT);
        if (more) loadAB(kt + 1);   // global prefetch overlaps MMA below

#pragma unroll
        for (int kk = 0; kk < 2; ++kk) {
            unsigned af[4][4], bf[4][2];
            const int kb = kk * 8 + tg;
#pragma unroll
            for (int mi = 0; mi < 4; mi++) {
                const int m0 = wm * 64 + mi * 16 + gq;
                af[mi][0] = As[buf][m0][kb];
                af[mi][1] = As[buf][m0 + 8][kb];
                af[mi][2] = As[buf][m0][kb + 4];
                af[mi][3] = As[buf][m0 + 8][kb + 4];
            }
#pragma unroll
            for (int ni = 0; ni < 4; ni++) {
                const int n0 = wn * 32 + ni * 8 + gq;
                bf[ni][0] = Bs[buf][kk * 8 + tg][n0];
                bf[ni][1] = Bs[buf][kk * 8 + tg + 4][n0];
            }
#pragma unroll
            for (int mi = 0; mi < 4; mi++)
#pragma unroll
                for (int ni = 0; ni < 4; ni++)
                    mma_tf32(acc[mi][ni], af[mi], bf[ni]);
        }

        if (more) {
            storeAB(buf ^ 1);   // writes the OTHER buffer: no pre-store sync needed
            __syncthreads();
        }
    }

    // epilogue: bias (+gelu), float2 stores
#pragma unroll
    for (int mi = 0; mi < 4; mi++) {
        const int r0 = bm + wm * 64 + mi * 16 + gq;
#pragma unroll
        for (int ni = 0; ni < 4; ni++) {
            const int c0 = bn + wn * 32 + ni * 8 + tg * 2;
            float b0 = 0.0f, b1 = 0.0f;
            if (bias) { b0 = bias[c0]; b1 = bias[c0 + 1]; }
            float v0 = acc[mi][ni][0] + b0;
            float v1 = acc[mi][ni][1] + b1;
            float v2 = acc[mi][ni][2] + b0;
            float v3 = acc[mi][ni][3] + b1;
            if (GELU) {
                v0 = gelu_f(v0); v1 = gelu_f(v1);
                v2 = gelu_f(v2); v3 = gelu_f(v3);
            }
            *(float2*)&C[(size_t)r0 * N + c0]       = make_float2(v0, v1);
            *(float2*)&C[(size_t)(r0 + 8) * N + c0] = make_float2(v2, v3);
        }
    }
}

// ---------------- fused residual add + LayerNorm (in place on x) ----------------
// x[row] = LN(x[row] + r[row])   ; one block (128 threads) per row of HD=512
__global__ void add_ln_kernel(float* __restrict__ x, const float* __restrict__ r, int rstride,
                              const float* __restrict__ gamma, const float* __restrict__ beta)
{
    __shared__ float s1[4], s2[4];
    const int row = blockIdx.x;
    const int t = threadIdx.x;

    float4 xv = *(const float4*)(x + (size_t)row * HD + t * 4);
    float4 rv = *(const float4*)(r + (size_t)row * rstride + t * 4);
    xv.x += rv.x; xv.y += rv.y; xv.z += rv.z; xv.w += rv.w;

    float s = xv.x + xv.y + xv.z + xv.w;
    float q = xv.x * xv.x + xv.y * xv.y + xv.z * xv.z + xv.w * xv.w;
#pragma unroll
    for (int o = 16; o; o >>= 1) {
        s += __shfl_xor_sync(0xffffffffu, s, o);
        q += __shfl_xor_sync(0xffffffffu, q, o);
    }
    if ((t & 31) == 0) { s1[t >> 5] = s; s2[t >> 5] = q; }
    __syncthreads();
    s = s1[0] + s1[1] + s1[2] + s1[3];
    q = s2[0] + s2[1] + s2[2] + s2[3];

    const float mean = s * (1.0f / HD);
    const float var  = q * (1.0f / HD) - mean * mean;
    const float rs   = rsqrtf(var + 1e-5f);

    float4 gv = *(const float4*)(gamma + t * 4);
    float4 bv = *(const float4*)(beta + t * 4);
    float4 ov;
    ov.x = (xv.x - mean) * rs * gv.x + bv.x;
    ov.y = (xv.y - mean) * rs * gv.y + bv.y;
    ov.z = (xv.z - mean) * rs * gv.z + bv.z;
    ov.w = (xv.w - mean) * rs * gv.w + bv.w;
    *(float4*)(x + (size_t)row * HD + t * 4) = ov;
}

// ---------------- folded attention bias: b_att = ao_w @ bv + ao_b ----------------
__global__ void fold_bias_kernel(const float* __restrict__ aow, const float* __restrict__ aob,
                                 const float* __restrict__ qkvb, float* __restrict__ batt)
{
    const int il = blockIdx.x;                     // 0..5 = i*3+l
    const float* aw = aow + (size_t)il * HD * HD;
    const float* ab = aob + (size_t)il * HD;
    const float* bv = qkvb + ((size_t)il * 3 + 2) * HD;   // wv bias slice
    const int m = threadIdx.x;
    float sum = ab[m];
    for (int j = 0; j < HD; j++) sum += aw[(size_t)m * HD + j] * bv[j];
    batt[(size_t)il * HD + m] = sum;
}

// ---------------- prior MLP (batch-invariant, 1 sample) ----------------
__global__ void prior_kernel(const float* __restrict__ emb,
                             const float* __restrict__ w1, const float* __restrict__ b1,
                             const float* __restrict__ w2, const float* __restrict__ b2,
                             float* __restrict__ out)
{
    __shared__ float pe[HD];
    __shared__ float ph[2 * HD];
    const int t = threadIdx.x;   // 1024 threads
    if (t < HD) pe[t] = emb[t];
    __syncthreads();
    float s = b1[t];
    for (int k = 0; k < HD; k++) s += pe[k] * w1[(size_t)t * HD + k];
    ph[t] = gelu_f(s);
    __syncthreads();
    float o = b2[t];
    for (int k = 0; k < 2 * HD; k++) o += ph[k] * w2[(size_t)t * 2 * HD + k];
    out[t] = o;
}

// ---------------- final combine: residual mix + missing_type select ----------------
__global__ void combine_kernel(const float* __restrict__ img, const float* __restrict__ txt,
                               const float* __restrict__ gen_t, const float* __restrict__ gen_i,
                               const float* __restrict__ prior, const float* __restrict__ rw,
                               const int* __restrict__ mt, float* __restrict__ out)
{
    const int idx = blockIdx.x * blockDim.x + threadIdx.x;
    if (idx >= BATCH * HD) return;
    const int b = idx >> 9;            // /HD
    const int j = idx & (HD - 1);
    const int m = mt[b];
    const float iv = img[idx], tv = txt[idx];
    const float r0 = rw[0], r1 = rw[1];
    const float gt = r0 * tv + (1.0f - r0) * gen_t[idx];   // cross_gen(0): rw*tgt + (1-rw)*gen
    const float gi = r1 * iv + (1.0f - r1) * gen_i[idx];
    const float ei = (m == 3) ? prior[j]       : ((m == 2) ? gi : iv);
    const float et = (m == 3) ? prior[HD + j]  : ((m == 1) ? gt : tv);
    out[idx] = ei;
    out[(size_t)BATCH * HD + idx] = et;
}

// ---------------- launch ----------------
extern "C" void kernel_launch(void* const* d_in, const int* in_sizes, int n_in,
                              void* d_out, int out_size)
{
    const float* image = (const float*)d_in[0];
    const float* text  = (const float*)d_in[1];
    const float* ipw   = (const float*)d_in[2];
    const float* ipb   = (const float*)d_in[3];
    const float* qkvw  = (const float*)d_in[4];
    const float* qkvb  = (const float*)d_in[5];
    const float* aow   = (const float*)d_in[6];
    const float* aob   = (const float*)d_in[7];
    const float* ln1g  = (const float*)d_in[8];
    const float* ln1b  = (const float*)d_in[9];
    const float* ln2g  = (const float*)d_in[10];
    const float* ln2b  = (const float*)d_in[11];
    const float* f1w   = (const float*)d_in[12];
    const float* f1b   = (const float*)d_in[13];
    const float* f2w   = (const float*)d_in[14];
    const float* f2b   = (const float*)d_in[15];
    const float* opw   = (const float*)d_in[16];
    const float* opb   = (const float*)d_in[17];
    const float* rw    = (const float*)d_in[18];
    const float* pw1   = (const float*)d_in[19];
    const float* pb1   = (const float*)d_in[20];
    const float* pw2   = (const float*)d_in[21];
    const float* pb2   = (const float*)d_in[22];
    const float* pemb  = (const float*)d_in[23];
    const int*   mt    = (const int*)d_in[24];
    float* out = (float*)d_out;

    float *Watt, *batt, *ATT, *X, *Hb, *T, *G0, *G1, *PR;
    cudaGetSymbolAddress((void**)&Watt, g_Watt);
    cudaGetSymbolAddress((void**)&batt, g_batt);
    cudaGetSymbolAddress((void**)&ATT,  g_ATT);
    cudaGetSymbolAddress((void**)&X,    g_X);
    cudaGetSymbolAddress((void**)&Hb,   g_Hbuf);
    cudaGetSymbolAddress((void**)&T,    g_T);
    cudaGetSymbolAddress((void**)&G0,   g_gen0);
    cudaGetSymbolAddress((void**)&G1,   g_gen1);
    cudaGetSymbolAddress((void**)&PR,   g_prior);

    // 1) fold attention biases:  b_att = ao_w @ bv + ao_b
    fold_bias_kernel<<<6, HD>>>(aow, aob, qkvb, batt);

    // 2) fold attention weights: W_att = ao_w @ wv   (plain matmul, TRANSB=0)
    for (int il = 0; il < 6; ++il) {
        gemm_kernel<false, false><<<dim3(4, 4), 256>>>(
            aow + (size_t)il * HD * HD,
            qkvw + ((size_t)il * 3 * HD + 2 * HD) * HD,   // wv slice [H,H]
            nullptr,
            Watt + (size_t)il * HD * HD,
            HD, HD, HD);
    }

    // 3) prior MLP (tiny, batch-invariant)
    prior_kernel<<<1, 1024>>>(pemb, pw1, pb1, pw2, pb2, PR);

    // 4) all-layer attention adds per generator: ATT[i] = tgt_i @ Watt_i.T + batt_i  (N=1536)
    const float* srcs[2] = {image, text};
    const float* tgts[2] = {text, image};
    for (int i = 0; i < 2; i++) {
        gemm_kernel<true, false><<<dim3(3 * HD / 128, BATCH / 128), 256>>>(
            tgts[i], Watt + (size_t)i * 3 * HD * HD, batt + (size_t)i * 3 * HD,
            ATT + (size_t)i * BATCH * 3 * HD, BATCH, 3 * HD, HD);
    }

    // 5) generators (sequential on stream, share scratch)
    float* gens[2] = {G0, G1};
    for (int i = 0; i < 2; i++) {
        // input projection
        gemm_kernel<true, false><<<dim3(HD / 128, BATCH / 128), 256>>>(
            srcs[i], ipw + (size_t)i * HD * HD, ipb + (size_t)i * HD, X, BATCH, HD, HD);
        for (int l = 0; l < NLAYER; l++) {
            const size_t il = (size_t)i * 3 + l;
            // x = LN(x + attn_l)
            add_ln_kernel<<<BATCH, 128>>>(
                X, ATT + (size_t)i * BATCH * 3 * HD + (size_t)l * HD, 3 * HD,
                ln1g + il * HD, ln1b + il * HD);
            // h = gelu(x @ f1w.T + f1b)
            gemm_kernel<true, true><<<dim3(FF / 128, BATCH / 128), 256>>>(
                X, f1w + il * FF * HD, f1b + il * FF, Hb, BATCH, FF, HD);
            // t = h @ f2w.T + f2b
            gemm_kernel<true, false><<<dim3(HD / 128, BATCH / 128), 256>>>(
                Hb, f2w + il * HD * FF, f2b + il * HD, T, BATCH, HD, FF);
            // x = LN(x + t)
            add_ln_kernel<<<BATCH, 128>>>(X, T, HD, ln2g + il * HD, ln2b + il * HD);
        }
        // output projection
        gemm_kernel<true, false><<<dim3(HD / 128, BATCH / 128), 256>>>(
            X, opw + (size_t)i * HD * HD, opb + (size_t)i * HD, gens[i], BATCH, HD, HD);
    }

    // 6) final mix + missing_type selection
    combine_kernel<<<(BATCH * HD + 255) / 256, 256>>>(image, text, G0, G1, PR, rw, mt, out);
}

// round 3
// speedup vs baseline: 1.3614x; 1.3614x over previous
#include <cuda_runtime.h>
#include <math.h>
#include <stdint.h>

#define HD 512
#define NLAYER 3
#define BATCH 16384
#define FF 2048   // 4*HD

// ---------------- device scratch (no allocations allowed) ----------------
__device__ float g_Watt[6 * HD * HD];                    // folded ao_w @ wv
__device__ float g_batt[6 * HD];                         // folded bias
__device__ float g_ATT[(size_t)2 * BATCH * 3 * HD];      // per-gen per-layer attention adds
__device__ float g_X[(size_t)2 * BATCH * HD];            // running activation (both gens)
__device__ float g_Hb[(size_t)2 * BATCH * FF];           // FFN hidden (both gens)
__device__ float g_T[(size_t)2 * BATCH * HD];            // FFN out temp (both gens)
__device__ float g_G[(size_t)2 * BATCH * HD];            // gen outputs (both gens)
__device__ float g_prior[2 * HD];                        // prior MLP output

// ---------------- helpers ----------------
__device__ __forceinline__ unsigned f2tf(float f) {
    unsigned u;
    asm("cvt.rna.tf32.f32 %0, %1;" : "=r"(u) : "f"(f));
    return u;
}
__device__ __forceinline__ float gelu_f(float x) {
    return 0.5f * x * (1.0f + erff(x * 0.70710678118654752f));
}
__device__ __forceinline__ void mma_tf32(float c[4], const unsigned a[4], const unsigned b[2]) {
    asm volatile(
        "mma.sync.aligned.m16n8k8.row.col.f32.tf32.tf32.f32 "
        "{%0,%1,%2,%3},{%4,%5,%6,%7},{%8,%9},{%0,%1,%2,%3};\n"
        : "+f"(c[0]), "+f"(c[1]), "+f"(c[2]), "+f"(c[3])
        : "r"(a[0]), "r"(a[1]), "r"(a[2]), "r"(a[3]), "r"(b[0]), "r"(b[1]));
}
__device__ __forceinline__ void cp_async16(uint32_t dst, const void* src) {
    asm volatile("cp.async.cg.shared.global [%0], [%1], 16;\n" :: "r"(dst), "l"(src));
}

// ================= main GEMM: C = A @ W^T + bias (opt GELU), batched over z ==========
// A = (z ? A1 : A0) + z*sA ; W row-major [N,K] (+ z*sW) ; C row-major [M,N] (+ z*sC)
// CTA tile 256x128, BK=16, 3-stage cp.async, warp tile 64x64 (8 warps, 4x2).
// Requires M%256==0, N%128==0, K%16==0, K/16 >= 2.
template <bool GELU>
__global__ void __launch_bounds__(256, 1) gemm2_kernel(
    const float* __restrict__ A0, const float* __restrict__ A1, size_t sA,
    const float* __restrict__ W, size_t sW,
    const float* __restrict__ bias, size_t sB,
    float* __restrict__ C, size_t sC,
    int M, int N, int K)
{
    constexpr int BM = 256, BN = 128, BK = 16, ST = 3, RS = 20;
    extern __shared__ float sm[];
    float* AsBase = sm;                      // [ST][BM][RS]
    float* BsBase = sm + ST * BM * RS;       // [ST][BN][RS]

    const int t    = threadIdx.x;
    const int lane = t & 31;
    const int warp = t >> 5;
    const int wm   = warp >> 1;   // 0..3
    const int wn   = warp & 1;    // 0..1
    const int gq   = lane >> 2;   // 0..7
    const int tg   = lane & 3;    // 0..3
    const int z    = blockIdx.z;

    const float* A  = (z ? A1 : A0) + (size_t)z * sA;
    const float* Wz = W + (size_t)z * sW;
    const float* bz = bias + (size_t)z * sB;
    float*       Cz = C + (size_t)z * sC;

    const int bm = blockIdx.y * BM;
    const int bn = blockIdx.x * BN;

    float acc[4][8][4];
#pragma unroll
    for (int a = 0; a < 4; a++)
#pragma unroll
        for (int b = 0; b < 8; b++)
#pragma unroll
            for (int c = 0; c < 4; c++) acc[a][b][c] = 0.0f;

    const int arow = t >> 2;   // 0..63
    const int ac4  = t & 3;    // 0..3

    auto stage_load = [&](int kt, int s) {
        float* as = AsBase + s * BM * RS;
        float* bs = BsBase + s * BN * RS;
        const float* ga = A + (size_t)(bm + arow) * K + kt * BK + ac4 * 4;
#pragma unroll
        for (int p = 0; p < 4; p++) {
            uint32_t dst = (uint32_t)__cvta_generic_to_shared(as + (arow + 64 * p) * RS + ac4 * 4);
            cp_async16(dst, ga + (size_t)(64 * p) * K);
        }
        const float* gb = Wz + (size_t)(bn + arow) * K + kt * BK + ac4 * 4;
#pragma unroll
        for (int p = 0; p < 2; p++) {
            uint32_t dst = (uint32_t)__cvta_generic_to_shared(bs + (arow + 64 * p) * RS + ac4 * 4);
            cp_async16(dst, gb + (size_t)(64 * p) * K);
        }
        asm volatile("cp.async.commit_group;\n" ::: "memory");
    };

    const int KT = K / BK;
    stage_load(0, 0);
    stage_load(1, 1);

    int sc = 0;
    for (int kt = 0; kt < KT; ++kt) {
        asm volatile("cp.async.wait_group %0;\n" :: "n"(1) : "memory");
        __syncthreads();
        if (kt + 2 < KT) stage_load(kt + 2, (sc + 2 >= ST) ? sc + 2 - ST : sc + 2);

        const float* as = AsBase + sc * BM * RS;
        const float* bs = BsBase + sc * BN * RS;
#pragma unroll
        for (int kk = 0; kk < 2; ++kk) {
            unsigned af[4][4], bf[8][2];
            const int kb = kk * 8 + tg;
#pragma unroll
            for (int mi = 0; mi < 4; mi++) {
                const int m0 = wm * 64 + mi * 16 + gq;
                af[mi][0] = f2tf(as[m0 * RS + kb]);
                af[mi][1] = f2tf(as[(m0 + 8) * RS + kb]);
                af[mi][2] = f2tf(as[m0 * RS + kb + 4]);
                af[mi][3] = f2tf(as[(m0 + 8) * RS + kb + 4]);
            }
#pragma unroll
            for (int ni = 0; ni < 8; ni++) {
                const int n0 = wn * 64 + ni * 8 + gq;
                bf[ni][0] = f2tf(bs[n0 * RS + kb]);
                bf[ni][1] = f2tf(bs[n0 * RS + kb + 4]);
            }
#pragma unroll
            for (int mi = 0; mi < 4; mi++)
#pragma unroll
                for (int ni = 0; ni < 8; ni++)
                    mma_tf32(acc[mi][ni], af[mi], bf[ni]);
        }
        sc = (sc + 1 >= ST) ? 0 : sc + 1;
    }

    // epilogue
#pragma unroll
    for (int mi = 0; mi < 4; mi++) {
        const int r0 = bm + wm * 64 + mi * 16 + gq;
#pragma unroll
        for (int ni = 0; ni < 8; ni++) {
            const int c0 = bn + wn * 64 + ni * 8 + tg * 2;
            const float b0 = bz[c0], b1 = bz[c0 + 1];
            float v0 = acc[mi][ni][0] + b0;
            float v1 = acc[mi][ni][1] + b1;
            float v2 = acc[mi][ni][2] + b0;
            float v3 = acc[mi][ni][3] + b1;
            if (GELU) {
                v0 = gelu_f(v0); v1 = gelu_f(v1);
                v2 = gelu_f(v2); v3 = gelu_f(v3);
            }
            *(float2*)&Cz[(size_t)r0 * N + c0]       = make_float2(v0, v1);
            *(float2*)&Cz[(size_t)(r0 + 8) * N + c0] = make_float2(v2, v3);
        }
    }
}

// ============ fold GEMM (tiny, batched over z=0..5): Watt[z] = ao_w[z] @ wv[z] =========
// Plain matmul: B'[k][n] = wv[k][n], wv row-major [K=H rows][N=H cols]. 128x128 tile.
__global__ void __launch_bounds__(256) fold_gemm_kernel(
    const float* __restrict__ aow, const float* __restrict__ qkvw, float* __restrict__ Watt)
{
    constexpr int BM = 128, BN = 128, BK = 16;
    const int M = HD, N = HD, K = HD;
    __shared__ unsigned As[2][BM][20];
    __shared__ unsigned Bs[2][BK][136];

    const int z = blockIdx.z;
    const float* A = aow + (size_t)z * HD * HD;
    const float* W = qkvw + (size_t)z * 3 * HD * HD + (size_t)2 * HD * HD;  // wv slice
    float* C = Watt + (size_t)z * HD * HD;

    const int t    = threadIdx.x;
    const int lane = t & 31;
    const int warp = t >> 5;
    const int wm   = warp >> 2;
    const int wn   = warp & 3;
    const int gq   = lane >> 2;
    const int tg   = lane & 3;
    const int bm = blockIdx.y * BM;
    const int bn = blockIdx.x * BN;

    float acc[4][4][4];
#pragma unroll
    for (int a = 0; a < 4; a++)
#pragma unroll
        for (int b = 0; b < 4; b++)
#pragma unroll
            for (int c = 0; c < 4; c++) acc[a][b][c] = 0.0f;

    const int ar  = t >> 2;
    const int ac4 = t & 3;
    const float* Abase = A + (size_t)(bm + ar) * K + ac4 * 4;

    float4 ra0, ra1, rb0, rb1;
    auto loadAB = [&](int kt) {
        const float* ap = Abase + kt * BK;
        ra0 = *(const float4*)(ap);
        ra1 = *(const float4*)(ap + (size_t)64 * K);
        const int k0 = t >> 5;
        const int c4 = t & 31;
        const float* bp = W + (size_t)(kt * BK + k0) * N + bn + c4 * 4;
        rb0 = *(const float4*)(bp);
        rb1 = *(const float4*)(bp + (size_t)8 * N);
    };
    auto storeAB = [&](int buf) {
        As[buf][ar][ac4 * 4 + 0]      = f2tf(ra0.x);
        As[buf][ar][ac4 * 4 + 1]      = f2tf(ra0.y);
        As[buf][ar][ac4 * 4 + 2]      = f2tf(ra0.z);
        As[buf][ar][ac4 * 4 + 3]      = f2tf(ra0.w);
        As[buf][ar + 64][ac4 * 4 + 0] = f2tf(ra1.x);
        As[buf][ar + 64][ac4 * 4 + 1] = f2tf(ra1.y);
        As[buf][ar + 64][ac4 * 4 + 2] = f2tf(ra1.z);
        As[buf][ar + 64][ac4 * 4 + 3] = f2tf(ra1.w);
        const int k0 = t >> 5;
        const int c4 = t & 31;
        Bs[buf][k0][c4 * 4 + 0]     = f2tf(rb0.x);
        Bs[buf][k0][c4 * 4 + 1]     = f2tf(rb0.y);
        Bs[buf][k0][c4 * 4 + 2]     = f2tf(rb0.z);
        Bs[buf][k0][c4 * 4 + 3]     = f2tf(rb0.w);
        Bs[buf][k0 + 8][c4 * 4 + 0] = f2tf(rb1.x);
        Bs[buf][k0 + 8][c4 * 4 + 1] = f2tf(rb1.y);
        Bs[buf][k0 + 8][c4 * 4 + 2] = f2tf(rb1.z);
        Bs[buf][k0 + 8][c4 * 4 + 3] = f2tf(rb1.w);
    };

    const int KT = K / BK;
    loadAB(0);
    storeAB(0);
    __syncthreads();

    for (int kt = 0; kt < KT; ++kt) {
        const int buf = kt & 1;
        const bool more = (kt + 1 < KT);
        if (more) loadAB(kt + 1);
#pragma unroll
        for (int kk = 0; kk < 2; ++kk) {
            unsigned af[4][4], bf[4][2];
            const int kb = kk * 8 + tg;
#pragma unroll
            for (int mi = 0; mi < 4; mi++) {
                const int m0 = wm * 64 + mi * 16 + gq;
                af[mi][0] = As[buf][m0][kb];
                af[mi][1] = As[buf][m0 + 8][kb];
                af[mi][2] = As[buf][m0][kb + 4];
                af[mi][3] = As[buf][m0 + 8][kb + 4];
            }
#pragma unroll
            for (int ni = 0; ni < 4; ni++) {
                const int n0 = wn * 32 + ni * 8 + gq;
                bf[ni][0] = Bs[buf][kk * 8 + tg][n0];
                bf[ni][1] = Bs[buf][kk * 8 + tg + 4][n0];
            }
#pragma unroll
            for (int mi = 0; mi < 4; mi++)
#pragma unroll
                for (int ni = 0; ni < 4; ni++)
                    mma_tf32(acc[mi][ni], af[mi], bf[ni]);
        }
        if (more) {
            storeAB(buf ^ 1);
            __syncthreads();
        }
    }

#pragma unroll
    for (int mi = 0; mi < 4; mi++) {
        const int r0 = bm + wm * 64 + mi * 16 + gq;
#pragma unroll
        for (int ni = 0; ni < 4; ni++) {
            const int c0 = bn + wn * 32 + ni * 8 + tg * 2;
            *(float2*)&C[(size_t)r0 * N + c0]       = make_float2(acc[mi][ni][0], acc[mi][ni][1]);
            *(float2*)&C[(size_t)(r0 + 8) * N + c0] = make_float2(acc[mi][ni][2], acc[mi][ni][3]);
        }
    }
}

// ---------------- fused residual add + LayerNorm (in place), batched over z ----------
__global__ void add_ln_kernel(float* __restrict__ x, size_t xzs,
                              const float* __restrict__ r, size_t rzs, int rstride,
                              const float* __restrict__ gamma, const float* __restrict__ beta,
                              size_t gzs)
{
    __shared__ float s1[4], s2[4];
    const int z = blockIdx.y;
    x += (size_t)z * xzs;
    r += (size_t)z * rzs;
    gamma += (size_t)z * gzs;
    beta  += (size_t)z * gzs;
    const int row = blockIdx.x;
    const int t = threadIdx.x;

    float4 xv = *(const float4*)(x + (size_t)row * HD + t * 4);
    float4 rv = *(const float4*)(r + (size_t)row * rstride + t * 4);
    xv.x += rv.x; xv.y += rv.y; xv.z += rv.z; xv.w += rv.w;

    float s = xv.x + xv.y + xv.z + xv.w;
    float q = xv.x * xv.x + xv.y * xv.y + xv.z * xv.z + xv.w * xv.w;
#pragma unroll
    for (int o = 16; o; o >>= 1) {
        s += __shfl_xor_sync(0xffffffffu, s, o);
        q += __shfl_xor_sync(0xffffffffu, q, o);
    }
    if ((t & 31) == 0) { s1[t >> 5] = s; s2[t >> 5] = q; }
    __syncthreads();
    s = s1[0] + s1[1] + s1[2] + s1[3];
    q = s2[0] + s2[1] + s2[2] + s2[3];

    const float mean = s * (1.0f / HD);
    const float var  = q * (1.0f / HD) - mean * mean;
    const float rs   = rsqrtf(var + 1e-5f);

    float4 gv = *(const float4*)(gamma + t * 4);
    float4 bv = *(const float4*)(beta + t * 4);
    float4 ov;
    ov.x = (xv.x - mean) * rs * gv.x + bv.x;
    ov.y = (xv.y - mean) * rs * gv.y + bv.y;
    ov.z = (xv.z - mean) * rs * gv.z + bv.z;
    ov.w = (xv.w - mean) * rs * gv.w + bv.w;
    *(float4*)(x + (size_t)row * HD + t * 4) = ov;
}

// ---------------- folded attention bias: b_att = ao_w @ bv + ao_b ----------------
__global__ void fold_bias_kernel(const float* __restrict__ aow, const float* __restrict__ aob,
                                 const float* __restrict__ qkvb, float* __restrict__ batt)
{
    const int il = blockIdx.x;
    const float* aw = aow + (size_t)il * HD * HD;
    const float* ab = aob + (size_t)il * HD;
    const float* bv = qkvb + ((size_t)il * 3 + 2) * HD;
    const int m = threadIdx.x;
    float sum = ab[m];
    for (int j = 0; j < HD; j++) sum += aw[(size_t)m * HD + j] * bv[j];
    batt[(size_t)il * HD + m] = sum;
}

// ---------------- prior MLP (batch-invariant) ----------------
__global__ void prior_kernel(const float* __restrict__ emb,
                             const float* __restrict__ w1, const float* __restrict__ b1,
                             const float* __restrict__ w2, const float* __restrict__ b2,
                             float* __restrict__ out)
{
    __shared__ float pe[HD];
    __shared__ float ph[2 * HD];
    const int t = threadIdx.x;   // 1024
    if (t < HD) pe[t] = emb[t];
    __syncthreads();
    float s = b1[t];
    for (int k = 0; k < HD; k++) s += pe[k] * w1[(size_t)t * HD + k];
    ph[t] = gelu_f(s);
    __syncthreads();
    float o = b2[t];
    for (int k = 0; k < 2 * HD; k++) o += ph[k] * w2[(size_t)t * 2 * HD + k];
    out[t] = o;
}

// ---------------- final combine ----------------
__global__ void combine_kernel(const float* __restrict__ img, const float* __restrict__ txt,
                               const float* __restrict__ gen_t, const float* __restrict__ gen_i,
                               const float* __restrict__ prior, const float* __restrict__ rw,
                               const int* __restrict__ mt, float* __restrict__ out)
{
    const int idx = blockIdx.x * blockDim.x + threadIdx.x;
    if (idx >= BATCH * HD) return;
    const int b = idx >> 9;
    const int j = idx & (HD - 1);
    const int m = mt[b];
    const float iv = img[idx], tv = txt[idx];
    const float r0 = rw[0], r1 = rw[1];
    const float gt = r0 * tv + (1.0f - r0) * gen_t[idx];
    const float gi = r1 * iv + (1.0f - r1) * gen_i[idx];
    const float ei = (m == 3) ? prior[j]      : ((m == 2) ? gi : iv);
    const float et = (m == 3) ? prior[HD + j] : ((m == 1) ? gt : tv);
    out[idx] = ei;
    out[(size_t)BATCH * HD + idx] = et;
}

// ---------------- launch ----------------
extern "C" void kernel_launch(void* const* d_in, const int* in_sizes, int n_in,
                              void* d_out, int out_size)
{
    const float* image = (const float*)d_in[0];
    const float* text  = (const float*)d_in[1];
    const float* ipw   = (const float*)d_in[2];
    const float* ipb   = (const float*)d_in[3];
    const float* qkvw  = (const float*)d_in[4];
    const float* qkvb  = (const float*)d_in[5];
    const float* aow   = (const float*)d_in[6];
    const float* aob   = (const float*)d_in[7];
    const float* ln1g  = (const float*)d_in[8];
    const float* ln1b  = (const float*)d_in[9];
    const float* ln2g  = (const float*)d_in[10];
    const float* ln2b  = (const float*)d_in[11];
    const float* f1w   = (const float*)d_in[12];
    const float* f1b   = (const float*)d_in[13];
    const float* f2w   = (const float*)d_in[14];
    const float* f2b   = (const float*)d_in[15];
    const float* opw   = (const float*)d_in[16];
    const float* opb   = (const float*)d_in[17];
    const float* rw    = (const float*)d_in[18];
    const float* pw1   = (const float*)d_in[19];
    const float* pb1   = (const float*)d_in[20];
    const float* pw2   = (const float*)d_in[21];
    const float* pb2   = (const float*)d_in[22];
    const float* pemb  = (const float*)d_in[23];
    const int*   mt    = (const int*)d_in[24];
    float* out = (float*)d_out;

    float *Watt, *batt, *ATT, *X, *Hb, *T, *G, *PR;
    cudaGetSymbolAddress((void**)&Watt, g_Watt);
    cudaGetSymbolAddress((void**)&batt, g_batt);
    cudaGetSymbolAddress((void**)&ATT,  g_ATT);
    cudaGetSymbolAddress((void**)&X,    g_X);
    cudaGetSymbolAddress((void**)&Hb,   g_Hb);
    cudaGetSymbolAddress((void**)&T,    g_T);
    cudaGetSymbolAddress((void**)&G,    g_G);
    cudaGetSymbolAddress((void**)&PR,   g_prior);

    const int SMEMSZ = 3 * (256 + 128) * 20 * 4;   // 92160 B
    cudaFuncSetAttribute(gemm2_kernel<false>, cudaFuncAttributeMaxDynamicSharedMemorySize, SMEMSZ);
    cudaFuncSetAttribute(gemm2_kernel<true>,  cudaFuncAttributeMaxDynamicSharedMemorySize, SMEMSZ);

    const size_t BH  = (size_t)BATCH * HD;
    const size_t BF  = (size_t)BATCH * FF;
    const size_t B3H = (size_t)BATCH * 3 * HD;

    // 1) fold weights + biases + prior (all tiny, front of the graph)
    fold_gemm_kernel<<<dim3(4, 4, 6), 256>>>(aow, qkvw, Watt);
    fold_bias_kernel<<<6, HD>>>(aow, aob, qkvb, batt);
    prior_kernel<<<1, 1024>>>(pemb, pw1, pb1, pw2, pb2, PR);

    // 2) all-layer attention adds, both gens: ATT[z] = tgt_z @ Watt_z.T + batt_z
    gemm2_kernel<false><<<dim3(3 * HD / 128, BATCH / 256, 2), 256, SMEMSZ>>>(
        text, image, 0, Watt, (size_t)3 * HD * HD, batt, (size_t)3 * HD,
        ATT, B3H, BATCH, 3 * HD, HD);

    // 3) input projection, both gens: X[z] = src_z @ ipw_z.T + ipb_z
    gemm2_kernel<false><<<dim3(HD / 128, BATCH / 256, 2), 256, SMEMSZ>>>(
        image, text, 0, ipw, (size_t)HD * HD, ipb, HD,
        X, BH, BATCH, HD, HD);

    for (int l = 0; l < NLAYER; l++) {
        // x = LN(x + attn_l)
        add_ln_kernel<<<dim3(BATCH, 2), 128>>>(
            X, BH, ATT + (size_t)l * HD, B3H, 3 * HD,
            ln1g + (size_t)l * HD, ln1b + (size_t)l * HD, (size_t)NLAYER * HD);
        // h = gelu(x @ f1w.T + f1b)
        gemm2_kernel<true><<<dim3(FF / 128, BATCH / 256, 2), 256, SMEMSZ>>>(
            X, X, BH, f1w + (size_t)l * FF * HD, (size_t)NLAYER * FF * HD,
            f1b + (size_t)l * FF, (size_t)NLAYER * FF,
            Hb, BF, BATCH, FF, HD);
        // t = h @ f2w.T + f2b
        gemm2_kernel<false><<<dim3(HD / 128, BATCH / 256, 2), 256, SMEMSZ>>>(
            Hb, Hb, BF, f2w + (size_t)l * HD * FF, (size_t)NLAYER * HD * FF,
            f2b + (size_t)l * HD, (size_t)NLAYER * HD,
            T, BH, BATCH, HD, FF);
        // x = LN(x + t)
        add_ln_kernel<<<dim3(BATCH, 2), 128>>>(
            X, BH, T, BH, HD,
            ln2g + (size_t)l * HD, ln2b + (size_t)l * HD, (size_t)NLAYER * HD);
    }

    // 4) output projection, both gens
    gemm2_kernel<false><<<dim3(HD / 128, BATCH / 256, 2), 256, SMEMSZ>>>(
        X, X, BH, opw, (size_t)HD * HD, opb, HD,
        G, BH, BATCH, HD, HD);

    // 5) final mix + missing_type selection
    combine_kernel<<<(BATCH * HD + 255) / 256, 256>>>(image, text, G, G + BH, PR, rw, mt, out);
}

// round 6
// speedup vs baseline: 1.4276x; 1.0487x over previous
#include <cuda_runtime.h>
#include <math.h>
#include <stdint.h>

#define HD 512
#define NLAYER 3
#define BATCH 16384
#define FF 2048   // 4*HD

// ---------------- device scratch (no allocations allowed) ----------------
__device__ float g_Watt[6 * HD * HD];                    // folded ao_w @ wv
__device__ float g_batt[6 * HD];                         // folded bias
__device__ float g_ATT[(size_t)2 * BATCH * 3 * HD];      // per-gen per-layer attention adds
__device__ float g_X[(size_t)2 * BATCH * HD];            // running activation (both gens)
__device__ float g_Hb[(size_t)2 * BATCH * FF];           // FFN hidden (both gens)
__device__ float g_T[(size_t)2 * BATCH * HD];            // FFN out temp (both gens)
__device__ float g_G[(size_t)2 * BATCH * HD];            // gen outputs (both gens)
__device__ float g_prior[2 * HD];                        // prior MLP output

// ---------------- helpers ----------------
__device__ __forceinline__ unsigned f2tf(float f) {
    unsigned u;
    asm("cvt.rna.tf32.f32 %0, %1;" : "=r"(u) : "f"(f));
    return u;
}
__device__ __forceinline__ float gelu_f(float x) {
    return 0.5f * x * (1.0f + erff(x * 0.70710678118654752f));
}
__device__ __forceinline__ void mma_tf32(float c[4], const unsigned a[4], const unsigned b[2]) {
    asm volatile(
        "mma.sync.aligned.m16n8k8.row.col.f32.tf32.tf32.f32 "
        "{%0,%1,%2,%3},{%4,%5,%6,%7},{%8,%9},{%0,%1,%2,%3};\n"
        : "+f"(c[0]), "+f"(c[1]), "+f"(c[2]), "+f"(c[3])
        : "r"(a[0]), "r"(a[1]), "r"(a[2]), "r"(a[3]), "r"(b[0]), "r"(b[1]));
}
__device__ __forceinline__ void cp_async16(uint32_t dst, const void* src) {
    asm volatile("cp.async.cg.shared.global [%0], [%1], 16;\n" :: "r"(dst), "l"(src));
}

// ================= main GEMM: C = A @ W^T + bias (opt GELU), batched over z ==========
// A = (z ? A1 : A0) + z*sA ; W row-major [N,K] (+ z*sW) ; C row-major [M,N] (+ z*sC)
// CTA tile 256x128, BK=16, 3-stage cp.async, warp tile 64x64 (8 warps, 4x2).
// tf32 path feeds RAW f32 bits to HMMA (hardware truncates mantissa -> rtz tf32):
// zero cvt instructions in the inner loop.
// Requires M%256==0, N%128==0, K%16==0, K/16 >= 2.
template <bool GELU>
__global__ void __launch_bounds__(256, 1) gemm2_kernel(
    const float* __restrict__ A0, const float* __restrict__ A1, size_t sA,
    const float* __restrict__ W, size_t sW,
    const float* __restrict__ bias, size_t sB,
    float* __restrict__ C, size_t sC,
    int M, int N, int K)
{
    constexpr int BM = 256, BN = 128, BK = 16, ST = 3, RS = 20;
    extern __shared__ float sm[];
    float* AsBase = sm;                      // [ST][BM][RS]
    float* BsBase = sm + ST * BM * RS;       // [ST][BN][RS]

    const int t    = threadIdx.x;
    const int lane = t & 31;
    const int warp = t >> 5;
    const int wm   = warp >> 1;   // 0..3
    const int wn   = warp & 1;    // 0..1
    const int gq   = lane >> 2;   // 0..7
    const int tg   = lane & 3;    // 0..3
    const int z    = blockIdx.z;

    const float* A  = (z ? A1 : A0) + (size_t)z * sA;
    const float* Wz = W + (size_t)z * sW;
    const float* bz = bias + (size_t)z * sB;
    float*       Cz = C + (size_t)z * sC;

    const int bm = blockIdx.y * BM;
    const int bn = blockIdx.x * BN;

    float acc[4][8][4];
#pragma unroll
    for (int a = 0; a < 4; a++)
#pragma unroll
        for (int b = 0; b < 8; b++)
#pragma unroll
            for (int c = 0; c < 4; c++) acc[a][b][c] = 0.0f;

    const int arow = t >> 2;   // 0..63
    const int ac4  = t & 3;    // 0..3

    // per-warp fragment base offsets (precomputed; inner loop adds constants only)
    const int aoff = (wm * 64 + gq) * RS + tg;   // + mi*16*RS (+8*RS) (+kk*8) (+4)
    const int boff = (wn * 64 + gq) * RS + tg;   // + ni*8*RS (+kk*8) (+4)

    auto stage_load = [&](int kt, int s) {
        float* as = AsBase + s * BM * RS;
        float* bs = BsBase + s * BN * RS;
        const float* ga = A + (size_t)(bm + arow) * K + kt * BK + ac4 * 4;
#pragma unroll
        for (int p = 0; p < 4; p++) {
            uint32_t dst = (uint32_t)__cvta_generic_to_shared(as + (arow + 64 * p) * RS + ac4 * 4);
            cp_async16(dst, ga + (size_t)(64 * p) * K);
        }
        const float* gb = Wz + (size_t)(bn + arow) * K + kt * BK + ac4 * 4;
#pragma unroll
        for (int p = 0; p < 2; p++) {
            uint32_t dst = (uint32_t)__cvta_generic_to_shared(bs + (arow + 64 * p) * RS + ac4 * 4);
            cp_async16(dst, gb + (size_t)(64 * p) * K);
        }
        asm volatile("cp.async.commit_group;\n" ::: "memory");
    };

    const int KT = K / BK;
    stage_load(0, 0);
    stage_load(1, 1);

    int sc = 0;
    for (int kt = 0; kt < KT; ++kt) {
        asm volatile("cp.async.wait_group %0;\n" :: "n"(1) : "memory");
        __syncthreads();
        if (kt + 2 < KT) stage_load(kt + 2, (sc + 2 >= ST) ? sc + 2 - ST : sc + 2);

        // raw f32 bits straight into HMMA (tf32 rtz) — no cvt in this loop
        const unsigned* as = (const unsigned*)(AsBase + sc * BM * RS) + aoff;
        const unsigned* bs = (const unsigned*)(BsBase + sc * BN * RS) + boff;

        unsigned af[2][4][4], bf[2][8][2];
#pragma unroll
        for (int kk = 0; kk < 2; ++kk) {
            const int kb = kk * 8;
#pragma unroll
            for (int mi = 0; mi < 4; mi++) {
                const unsigned* ap = as + mi * (16 * RS) + kb;
                af[kk][mi][0] = ap[0];
                af[kk][mi][1] = ap[8 * RS];
                af[kk][mi][2] = ap[4];
                af[kk][mi][3] = ap[8 * RS + 4];
            }
#pragma unroll
            for (int ni = 0; ni < 8; ni++) {
                const unsigned* bp = bs + ni * (8 * RS) + kb;
                bf[kk][ni][0] = bp[0];
                bf[kk][ni][1] = bp[4];
            }
        }
#pragma unroll
        for (int kk = 0; kk < 2; ++kk)
#pragma unroll
            for (int mi = 0; mi < 4; mi++)
#pragma unroll
                for (int ni = 0; ni < 8; ni++)
                    mma_tf32(acc[mi][ni], af[kk][mi], bf[kk][ni]);

        sc = (sc + 1 >= ST) ? 0 : sc + 1;
    }

    // epilogue
#pragma unroll
    for (int mi = 0; mi < 4; mi++) {
        const int r0 = bm + wm * 64 + mi * 16 + gq;
#pragma unroll
        for (int ni = 0; ni < 8; ni++) {
            const int c0 = bn + wn * 64 + ni * 8 + tg * 2;
            const float b0 = bz[c0], b1 = bz[c0 + 1];
            float v0 = acc[mi][ni][0] + b0;
            float v1 = acc[mi][ni][1] + b1;
            float v2 = acc[mi][ni][2] + b0;
            float v3 = acc[mi][ni][3] + b1;
            if (GELU) {
                v0 = gelu_f(v0); v1 = gelu_f(v1);
                v2 = gelu_f(v2); v3 = gelu_f(v3);
            }
            *(float2*)&Cz[(size_t)r0 * N + c0]       = make_float2(v0, v1);
            *(float2*)&Cz[(size_t)(r0 + 8) * N + c0] = make_float2(v2, v3);
        }
    }
}

// ============ fold GEMM (tiny, batched over z=0..5): Watt[z] = ao_w[z] @ wv[z] =========
__global__ void __launch_bounds__(256) fold_gemm_kernel(
    const float* __restrict__ aow, const float* __restrict__ qkvw, float* __restrict__ Watt)
{
    constexpr int BM = 128, BN = 128, BK = 16;
    const int N = HD, K = HD;
    __shared__ unsigned As[2][BM][20];
    __shared__ unsigned Bs[2][BK][136];

    const int z = blockIdx.z;
    const float* A = aow + (size_t)z * HD * HD;
    const float* W = qkvw + (size_t)z * 3 * HD * HD + (size_t)2 * HD * HD;  // wv slice
    float* C = Watt + (size_t)z * HD * HD;

    const int t    = threadIdx.x;
    const int lane = t & 31;
    const int warp = t >> 5;
    const int wm   = warp >> 2;
    const int wn   = warp & 3;
    const int gq   = lane >> 2;
    const int tg   = lane & 3;
    const int bm = blockIdx.y * BM;
    const int bn = blockIdx.x * BN;

    float acc[4][4][4];
#pragma unroll
    for (int a = 0; a < 4; a++)
#pragma unroll
        for (int b = 0; b < 4; b++)
#pragma unroll
            for (int c = 0; c < 4; c++) acc[a][b][c] = 0.0f;

    const int ar  = t >> 2;
    const int ac4 = t & 3;
    const float* Abase = A + (size_t)(bm + ar) * K + ac4 * 4;

    float4 ra0, ra1, rb0, rb1;
    auto loadAB = [&](int kt) {
        const float* ap = Abase + kt * BK;
        ra0 = *(const float4*)(ap);
        ra1 = *(const float4*)(ap + (size_t)64 * K);
        const int k0 = t >> 5;
        const int c4 = t & 31;
        const float* bp = W + (size_t)(kt * BK + k0) * N + bn + c4 * 4;
        rb0 = *(const float4*)(bp);
        rb1 = *(const float4*)(bp + (size_t)8 * N);
    };
    auto storeAB = [&](int buf) {
        As[buf][ar][ac4 * 4 + 0]      = f2tf(ra0.x);
        As[buf][ar][ac4 * 4 + 1]      = f2tf(ra0.y);
        As[buf][ar][ac4 * 4 + 2]      = f2tf(ra0.z);
        As[buf][ar][ac4 * 4 + 3]      = f2tf(ra0.w);
        As[buf][ar + 64][ac4 * 4 + 0] = f2tf(ra1.x);
        As[buf][ar + 64][ac4 * 4 + 1] = f2tf(ra1.y);
        As[buf][ar + 64][ac4 * 4 + 2] = f2tf(ra1.z);
        As[buf][ar + 64][ac4 * 4 + 3] = f2tf(ra1.w);
        const int k0 = t >> 5;
        const int c4 = t & 31;
        Bs[buf][k0][c4 * 4 + 0]     = f2tf(rb0.x);
        Bs[buf][k0][c4 * 4 + 1]     = f2tf(rb0.y);
        Bs[buf][k0][c4 * 4 + 2]     = f2tf(rb0.z);
        Bs[buf][k0][c4 * 4 + 3]     = f2tf(rb0.w);
        Bs[buf][k0 + 8][c4 * 4 + 0] = f2tf(rb1.x);
        Bs[buf][k0 + 8][c4 * 4 + 1] = f2tf(rb1.y);
        Bs[buf][k0 + 8][c4 * 4 + 2] = f2tf(rb1.z);
        Bs[buf][k0 + 8][c4 * 4 + 3] = f2tf(rb1.w);
    };

    const int KT = K / BK;
    loadAB(0);
    storeAB(0);
    __syncthreads();

    for (int kt = 0; kt < KT; ++kt) {
        const int buf = kt & 1;
        const bool more = (kt + 1 < KT);
        if (more) loadAB(kt + 1);
#pragma unroll
        for (int kk = 0; kk < 2; ++kk) {
            unsigned af[4][4], bf[4][2];
            const int kb = kk * 8 + tg;
#pragma unroll
            for (int mi = 0; mi < 4; mi++) {
                const int m0 = wm * 64 + mi * 16 + gq;
                af[mi][0] = As[buf][m0][kb];
                af[mi][1] = As[buf][m0 + 8][kb];
                af[mi][2] = As[buf][m0][kb + 4];
                af[mi][3] = As[buf][m0 + 8][kb + 4];
            }
#pragma unroll
            for (int ni = 0; ni < 4; ni++) {
                const int n0 = wn * 32 + ni * 8 + gq;
                bf[ni][0] = Bs[buf][kk * 8 + tg][n0];
                bf[ni][1] = Bs[buf][kk * 8 + tg + 4][n0];
            }
#pragma unroll
            for (int mi = 0; mi < 4; mi++)
#pragma unroll
                for (int ni = 0; ni < 4; ni++)
                    mma_tf32(acc[mi][ni], af[mi], bf[ni]);
        }
        if (more) {
            storeAB(buf ^ 1);
            __syncthreads();
        }
    }

#pragma unroll
    for (int mi = 0; mi < 4; mi++) {
        const int r0 = bm + wm * 64 + mi * 16 + gq;
#pragma unroll
        for (int ni = 0; ni < 4; ni++) {
            const int c0 = bn + wn * 32 + ni * 8 + tg * 2;
            *(float2*)&C[(size_t)r0 * N + c0]       = make_float2(acc[mi][ni][0], acc[mi][ni][1]);
            *(float2*)&C[(size_t)(r0 + 8) * N + c0] = make_float2(acc[mi][ni][2], acc[mi][ni][3]);
        }
    }
}

// ---------------- fused residual add + LayerNorm (in place), batched over z ----------
__global__ void add_ln_kernel(float* __restrict__ x, size_t xzs,
                              const float* __restrict__ r, size_t rzs, int rstride,
                              const float* __restrict__ gamma, const float* __restrict__ beta,
                              size_t gzs)
{
    __shared__ float s1[4], s2[4];
    const int z = blockIdx.y;
    x += (size_t)z * xzs;
    r += (size_t)z * rzs;
    gamma += (size_t)z * gzs;
    beta  += (size_t)z * gzs;
    const int row = blockIdx.x;
    const int t = threadIdx.x;

    float4 xv = *(const float4*)(x + (size_t)row * HD + t * 4);
    float4 rv = *(const float4*)(r + (size_t)row * rstride + t * 4);
    xv.x += rv.x; xv.y += rv.y; xv.z += rv.z; xv.w += rv.w;

    float s = xv.x + xv.y + xv.z + xv.w;
    float q = xv.x * xv.x + xv.y * xv.y + xv.z * xv.z + xv.w * xv.w;
#pragma unroll
    for (int o = 16; o; o >>= 1) {
        s += __shfl_xor_sync(0xffffffffu, s, o);
        q += __shfl_xor_sync(0xffffffffu, q, o);
    }
    if ((t & 31) == 0) { s1[t >> 5] = s; s2[t >> 5] = q; }
    __syncthreads();
    s = s1[0] + s1[1] + s1[2] + s1[3];
    q = s2[0] + s2[1] + s2[2] + s2[3];

    const float mean = s * (1.0f / HD);
    const float var  = q * (1.0f / HD) - mean * mean;
    const float rs   = rsqrtf(var + 1e-5f);

    float4 gv = *(const float4*)(gamma + t * 4);
    float4 bv = *(const float4*)(beta + t * 4);
    float4 ov;
    ov.x = (xv.x - mean) * rs * gv.x + bv.x;
    ov.y = (xv.y - mean) * rs * gv.y + bv.y;
    ov.z = (xv.z - mean) * rs * gv.z + bv.z;
    ov.w = (xv.w - mean) * rs * gv.w + bv.w;
    *(float4*)(x + (size_t)row * HD + t * 4) = ov;
}

// ---------------- folded attention bias: b_att = ao_w @ bv + ao_b ----------------
__global__ void fold_bias_kernel(const float* __restrict__ aow, const float* __restrict__ aob,
                                 const float* __restrict__ qkvb, float* __restrict__ batt)
{
    const int il = blockIdx.x;
    const float* aw = aow + (size_t)il * HD * HD;
    const float* ab = aob + (size_t)il * HD;
    const float* bv = qkvb + ((size_t)il * 3 + 2) * HD;
    const int m = threadIdx.x;
    float sum = ab[m];
    for (int j = 0; j < HD; j++) sum += aw[(size_t)m * HD + j] * bv[j];
    batt[(size_t)il * HD + m] = sum;
}

// ---------------- prior MLP (batch-invariant) ----------------
__global__ void prior_kernel(const float* __restrict__ emb,
                             const float* __restrict__ w1, const float* __restrict__ b1,
                             const float* __restrict__ w2, const float* __restrict__ b2,
                             float* __restrict__ out)
{
    __shared__ float pe[HD];
    __shared__ float ph[2 * HD];
    const int t = threadIdx.x;   // 1024
    if (t < HD) pe[t] = emb[t];
    __syncthreads();
    float s = b1[t];
    for (int k = 0; k < HD; k++) s += pe[k] * w1[(size_t)t * HD + k];
    ph[t] = gelu_f(s);
    __syncthreads();
    float o = b2[t];
    for (int k = 0; k < 2 * HD; k++) o += ph[k] * w2[(size_t)t * 2 * HD + k];
    out[t] = o;
}

// ---------------- final combine ----------------
__global__ void combine_kernel(const float* __restrict__ img, const float* __restrict__ txt,
                               const float* __restrict__ gen_t, const float* __restrict__ gen_i,
                               const float* __restrict__ prior, const float* __restrict__ rw,
                               const int* __restrict__ mt, float* __restrict__ out)
{
    const int idx = blockIdx.x * blockDim.x + threadIdx.x;
    if (idx >= BATCH * HD) return;
    const int b = idx >> 9;
    const int j = idx & (HD - 1);
    const int m = mt[b];
    const float iv = img[idx], tv = txt[idx];
    const float r0 = rw[0], r1 = rw[1];
    const float gt = r0 * tv + (1.0f - r0) * gen_t[idx];
    const float gi = r1 * iv + (1.0f - r1) * gen_i[idx];
    const float ei = (m == 3) ? prior[j]      : ((m == 2) ? gi : iv);
    const float et = (m == 3) ? prior[HD + j] : ((m == 1) ? gt : tv);
    out[idx] = ei;
    out[(size_t)BATCH * HD + idx] = et;
}

// ---------------- launch ----------------
extern "C" void kernel_launch(void* const* d_in, const int* in_sizes, int n_in,
                              void* d_out, int out_size)
{
    const float* image = (const float*)d_in[0];
    const float* text  = (const float*)d_in[1];
    const float* ipw   = (const float*)d_in[2];
    const float* ipb   = (const float*)d_in[3];
    const float* qkvw  = (const float*)d_in[4];
    const float* qkvb  = (const float*)d_in[5];
    const float* aow   = (const float*)d_in[6];
    const float* aob   = (const float*)d_in[7];
    const float* ln1g  = (const float*)d_in[8];
    const float* ln1b  = (const float*)d_in[9];
    const float* ln2g  = (const float*)d_in[10];
    const float* ln2b  = (const float*)d_in[11];
    const float* f1w   = (const float*)d_in[12];
    const float* f1b   = (const float*)d_in[13];
    const float* f2w   = (const float*)d_in[14];
    const float* f2b   = (const float*)d_in[15];
    const float* opw   = (const float*)d_in[16];
    const float* opb   = (const float*)d_in[17];
    const float* rw    = (const float*)d_in[18];
    const float* pw1   = (const float*)d_in[19];
    const float* pb1   = (const float*)d_in[20];
    const float* pw2   = (const float*)d_in[21];
    const float* pb2   = (const float*)d_in[22];
    const float* pemb  = (const float*)d_in[23];
    const int*   mt    = (const int*)d_in[24];
    float* out = (float*)d_out;

    float *Watt, *batt, *ATT, *X, *Hb, *T, *G, *PR;
    cudaGetSymbolAddress((void**)&Watt, g_Watt);
    cudaGetSymbolAddress((void**)&batt, g_batt);
    cudaGetSymbolAddress((void**)&ATT,  g_ATT);
    cudaGetSymbolAddress((void**)&X,    g_X);
    cudaGetSymbolAddress((void**)&Hb,   g_Hb);
    cudaGetSymbolAddress((void**)&T,    g_T);
    cudaGetSymbolAddress((void**)&G,    g_G);
    cudaGetSymbolAddress((void**)&PR,   g_prior);

    const int SMEMSZ = 3 * (256 + 128) * 20 * 4;   // 92160 B
    cudaFuncSetAttribute(gemm2_kernel<false>, cudaFuncAttributeMaxDynamicSharedMemorySize, SMEMSZ);
    cudaFuncSetAttribute(gemm2_kernel<true>,  cudaFuncAttributeMaxDynamicSharedMemorySize, SMEMSZ);

    const size_t BH  = (size_t)BATCH * HD;
    const size_t BF  = (size_t)BATCH * FF;
    const size_t B3H = (size_t)BATCH * 3 * HD;

    // 1) fold weights + biases + prior (tiny, front of the graph)
    fold_gemm_kernel<<<dim3(4, 4, 6), 256>>>(aow, qkvw, Watt);
    fold_bias_kernel<<<6, HD>>>(aow, aob, qkvb, batt);
    prior_kernel<<<1, 1024>>>(pemb, pw1, pb1, pw2, pb2, PR);

    // 2) all-layer attention adds, both gens: ATT[z] = tgt_z @ Watt_z.T + batt_z
    gemm2_kernel<false><<<dim3(3 * HD / 128, BATCH / 256, 2), 256, SMEMSZ>>>(
        text, image, 0, Watt, (size_t)3 * HD * HD, batt, (size_t)3 * HD,
        ATT, B3H, BATCH, 3 * HD, HD);

    // 3) input projection, both gens: X[z] = src_z @ ipw_z.T + ipb_z
    gemm2_kernel<false><<<dim3(HD / 128, BATCH / 256, 2), 256, SMEMSZ>>>(
        image, text, 0, ipw, (size_t)HD * HD, ipb, HD,
        X, BH, BATCH, HD, HD);

    for (int l = 0; l < NLAYER; l++) {
        // x = LN(x + attn_l)
        add_ln_kernel<<<dim3(BATCH, 2), 128>>>(
            X, BH, ATT + (size_t)l * HD, B3H, 3 * HD,
            ln1g + (size_t)l * HD, ln1b + (size_t)l * HD, (size_t)NLAYER * HD);
        // h = gelu(x @ f1w.T + f1b)
        gemm2_kernel<true><<<dim3(FF / 128, BATCH / 256, 2), 256, SMEMSZ>>>(
            X, X, BH, f1w + (size_t)l * FF * HD, (size_t)NLAYER * FF * HD,
            f1b + (size_t)l * FF, (size_t)NLAYER * FF,
            Hb, BF, BATCH, FF, HD);
        // t = h @ f2w.T + f2b
        gemm2_kernel<false><<<dim3(HD / 128, BATCH / 256, 2), 256, SMEMSZ>>>(
            Hb, Hb, BF, f2w + (size_t)l * HD * FF, (size_t)NLAYER * HD * FF,
            f2b + (size_t)l * HD, (size_t)NLAYER * HD,
            T, BH, BATCH, HD, FF);
        // x = LN(x + t)
        add_ln_kernel<<<dim3(BATCH, 2), 128>>>(
            X, BH, T, BH, HD,
            ln2g + (size_t)l * HD, ln2b + (size_t)l * HD, (size_t)NLAYER * HD);
    }

    // 4) output projection, both gens
    gemm2_kernel<false><<<dim3(HD / 128, BATCH / 256, 2), 256, SMEMSZ>>>(
        X, X, BH, opw, (size_t)HD * HD, opb, HD,
        G, BH, BATCH, HD, HD);

    // 5) final mix + missing_type selection
    combine_kernel<<<(BATCH * HD + 255) / 256, 256>>>(image, text, G, G + BH, PR, rw, mt, out);
}

// round 8
// speedup vs baseline: 1.5566x; 1.0904x over previous
#include <cuda_runtime.h>
#include <math.h>
#include <stdint.h>

#define HD 512
#define NLAYER 3
#define BATCH 16384
#define FF 2048   // 4*HD

// ---------------- device scratch (no allocations allowed) ----------------
__device__ float g_Watt[6 * HD * HD];                    // folded ao_w @ wv
__device__ float g_batt[6 * HD];                         // folded bias
__device__ float g_ATT[(size_t)2 * BATCH * 3 * HD];      // per-gen per-layer attention adds
__device__ float g_X[(size_t)2 * BATCH * HD];            // running activation (both gens)
__device__ float g_Hb[(size_t)2 * BATCH * FF];           // FFN hidden (both gens)
__device__ float g_T[(size_t)2 * BATCH * HD];            // FFN out temp (both gens)
__device__ float g_G[(size_t)2 * BATCH * HD];            // gen outputs (both gens)
__device__ float g_prior[2 * HD];                        // prior MLP output

// ---------------- helpers ----------------
__device__ __forceinline__ unsigned f2tf(float f) {
    unsigned u;
    asm("cvt.rna.tf32.f32 %0, %1;" : "=r"(u) : "f"(f));
    return u;
}
__device__ __forceinline__ float gelu_f(float x) {
    return 0.5f * x * (1.0f + erff(x * 0.70710678118654752f));
}
__device__ __forceinline__ void mma_tf32(float c[4], const unsigned a[4], const unsigned b[2]) {
    asm volatile(
        "mma.sync.aligned.m16n8k8.row.col.f32.tf32.tf32.f32 "
        "{%0,%1,%2,%3},{%4,%5,%6,%7},{%8,%9},{%0,%1,%2,%3};\n"
        : "+f"(c[0]), "+f"(c[1]), "+f"(c[2]), "+f"(c[3])
        : "r"(a[0]), "r"(a[1]), "r"(a[2]), "r"(a[3]), "r"(b[0]), "r"(b[1]));
}
__device__ __forceinline__ void cp_async16(uint32_t dst, const void* src) {
    asm volatile("cp.async.cg.shared.global [%0], [%1], 16;\n" :: "r"(dst), "l"(src));
}

// ================= main GEMM: C = A @ W^T + bias (opt GELU), batched over z ==========
// A = (z ? A1 : A0) + z*sA ; W row-major [N,K] (+ z*sW) ; C row-major [M,N] (+ z*sC)
// CTA tile 128x128, 128 threads (4 warps, warp tile 64x64), BK=16, 4-stage cp.async.
// 2 CTAs/SM so barrier/pipeline stalls of one CTA overlap the other's MMA stream.
// tf32 path feeds RAW f32 bits to HMMA (HW truncates mantissa -> rtz tf32).
// Requires M%128==0, N%128==0, K%16==0, K/16 >= 3.
template <bool GELU>
__global__ void __launch_bounds__(128, 2) gemm2_kernel(
    const float* __restrict__ A0, const float* __restrict__ A1, size_t sA,
    const float* __restrict__ W, size_t sW,
    const float* __restrict__ bias, size_t sB,
    float* __restrict__ C, size_t sC,
    int M, int N, int K)
{
    constexpr int BM = 128, BN = 128, BK = 16, ST = 4, RS = 20;
    extern __shared__ float sm[];
    float* AsBase = sm;                      // [ST][BM][RS]
    float* BsBase = sm + ST * BM * RS;       // [ST][BN][RS]

    const int t    = threadIdx.x;
    const int lane = t & 31;
    const int warp = t >> 5;      // 0..3
    const int wm   = warp >> 1;   // 0..1
    const int wn   = warp & 1;    // 0..1
    const int gq   = lane >> 2;   // 0..7
    const int tg   = lane & 3;    // 0..3
    const int z    = blockIdx.z;

    const float* A  = (z ? A1 : A0) + (size_t)z * sA;
    const float* Wz = W + (size_t)z * sW;
    const float* bz = bias + (size_t)z * sB;
    float*       Cz = C + (size_t)z * sC;

    const int bm = blockIdx.y * BM;
    const int bn = blockIdx.x * BN;

    float acc[4][8][4];
#pragma unroll
    for (int a = 0; a < 4; a++)
#pragma unroll
        for (int b = 0; b < 8; b++)
#pragma unroll
            for (int c = 0; c < 4; c++) acc[a][b][c] = 0.0f;

    const int arow = t >> 2;   // 0..31
    const int ac4  = t & 3;    // 0..3

    // per-warp fragment base offsets
    const int aoff = (wm * 64 + gq) * RS + tg;   // + mi*16*RS (+8*RS) (+kk*8) (+4)
    const int boff = (wn * 64 + gq) * RS + tg;   // + ni*8*RS (+kk*8) (+4)

    auto stage_load = [&](int kt, int s) {
        float* as = AsBase + s * BM * RS;
        float* bs = BsBase + s * BN * RS;
        const float* ga = A + (size_t)(bm + arow) * K + kt * BK + ac4 * 4;
#pragma unroll
        for (int p = 0; p < 4; p++) {
            uint32_t dst = (uint32_t)__cvta_generic_to_shared(as + (arow + 32 * p) * RS + ac4 * 4);
            cp_async16(dst, ga + (size_t)(32 * p) * K);
        }
        const float* gb = Wz + (size_t)(bn + arow) * K + kt * BK + ac4 * 4;
#pragma unroll
        for (int p = 0; p < 4; p++) {
            uint32_t dst = (uint32_t)__cvta_generic_to_shared(bs + (arow + 32 * p) * RS + ac4 * 4);
            cp_async16(dst, gb + (size_t)(32 * p) * K);
        }
        asm volatile("cp.async.commit_group;\n" ::: "memory");
    };

    const int KT = K / BK;
    stage_load(0, 0);
    stage_load(1, 1);
    stage_load(2, 2);

    int sc = 0;
    for (int kt = 0; kt < KT; ++kt) {
        asm volatile("cp.async.wait_group %0;\n" :: "n"(2) : "memory");
        __syncthreads();
        if (kt + 3 < KT) stage_load(kt + 3, (sc + 3) & (ST - 1));

        // raw f32 bits straight into HMMA (tf32 rtz) — no cvt in this loop
        const unsigned* as = (const unsigned*)(AsBase + sc * BM * RS) + aoff;
        const unsigned* bs = (const unsigned*)(BsBase + sc * BN * RS) + boff;

        unsigned af[2][4][4], bf[2][8][2];
#pragma unroll
        for (int kk = 0; kk < 2; ++kk) {
            const int kb = kk * 8;
#pragma unroll
            for (int mi = 0; mi < 4; mi++) {
                const unsigned* ap = as + mi * (16 * RS) + kb;
                af[kk][mi][0] = ap[0];
                af[kk][mi][1] = ap[8 * RS];
                af[kk][mi][2] = ap[4];
                af[kk][mi][3] = ap[8 * RS + 4];
            }
#pragma unroll
            for (int ni = 0; ni < 8; ni++) {
                const unsigned* bp = bs + ni * (8 * RS) + kb;
                bf[kk][ni][0] = bp[0];
                bf[kk][ni][1] = bp[4];
            }
        }
#pragma unroll
        for (int kk = 0; kk < 2; ++kk)
#pragma unroll
            for (int mi = 0; mi < 4; mi++)
#pragma unroll
                for (int ni = 0; ni < 8; ni++)
                    mma_tf32(acc[mi][ni], af[kk][mi], bf[kk][ni]);

        sc = (sc + 1) & (ST - 1);
    }

    // epilogue
#pragma unroll
    for (int mi = 0; mi < 4; mi++) {
        const int r0 = bm + wm * 64 + mi * 16 + gq;
#pragma unroll
        for (int ni = 0; ni < 8; ni++) {
            const int c0 = bn + wn * 64 + ni * 8 + tg * 2;
            const float b0 = bz[c0], b1 = bz[c0 + 1];
            float v0 = acc[mi][ni][0] + b0;
            float v1 = acc[mi][ni][1] + b1;
            float v2 = acc[mi][ni][2] + b0;
            float v3 = acc[mi][ni][3] + b1;
            if (GELU) {
                v0 = gelu_f(v0); v1 = gelu_f(v1);
                v2 = gelu_f(v2); v3 = gelu_f(v3);
            }
            *(float2*)&Cz[(size_t)r0 * N + c0]       = make_float2(v0, v1);
            *(float2*)&Cz[(size_t)(r0 + 8) * N + c0] = make_float2(v2, v3);
        }
    }
}

// ============ fold GEMM (tiny, batched over z=0..5): Watt[z] = ao_w[z] @ wv[z] =========
__global__ void __launch_bounds__(256) fold_gemm_kernel(
    const float* __restrict__ aow, const float* __restrict__ qkvw, float* __restrict__ Watt)
{
    constexpr int BM = 128, BN = 128, BK = 16;
    const int N = HD, K = HD;
    __shared__ unsigned As[2][BM][20];
    __shared__ unsigned Bs[2][BK][136];

    const int z = blockIdx.z;
    const float* A = aow + (size_t)z * HD * HD;
    const float* W = qkvw + (size_t)z * 3 * HD * HD + (size_t)2 * HD * HD;  // wv slice
    float* C = Watt + (size_t)z * HD * HD;

    const int t    = threadIdx.x;
    const int lane = t & 31;
    const int warp = t >> 5;
    const int wm   = warp >> 2;
    const int wn   = warp & 3;
    const int gq   = lane >> 2;
    const int tg   = lane & 3;
    const int bm = blockIdx.y * BM;
    const int bn = blockIdx.x * BN;

    float acc[4][4][4];
#pragma unroll
    for (int a = 0; a < 4; a++)
#pragma unroll
        for (int b = 0; b < 4; b++)
#pragma unroll
            for (int c = 0; c < 4; c++) acc[a][b][c] = 0.0f;

    const int ar  = t >> 2;
    const int ac4 = t & 3;
    const float* Abase = A + (size_t)(bm + ar) * K + ac4 * 4;

    float4 ra0, ra1, rb0, rb1;
    auto loadAB = [&](int kt) {
        const float* ap = Abase + kt * BK;
        ra0 = *(const float4*)(ap);
        ra1 = *(const float4*)(ap + (size_t)64 * K);
        const int k0 = t >> 5;
        const int c4 = t & 31;
        const float* bp = W + (size_t)(kt * BK + k0) * N + bn + c4 * 4;
        rb0 = *(const float4*)(bp);
        rb1 = *(const float4*)(bp + (size_t)8 * N);
    };
    auto storeAB = [&](int buf) {
        As[buf][ar][ac4 * 4 + 0]      = f2tf(ra0.x);
        As[buf][ar][ac4 * 4 + 1]      = f2tf(ra0.y);
        As[buf][ar][ac4 * 4 + 2]      = f2tf(ra0.z);
        As[buf][ar][ac4 * 4 + 3]      = f2tf(ra0.w);
        As[buf][ar + 64][ac4 * 4 + 0] = f2tf(ra1.x);
        As[buf][ar + 64][ac4 * 4 + 1] = f2tf(ra1.y);
        As[buf][ar + 64][ac4 * 4 + 2] = f2tf(ra1.z);
        As[buf][ar + 64][ac4 * 4 + 3] = f2tf(ra1.w);
        const int k0 = t >> 5;
        const int c4 = t & 31;
        Bs[buf][k0][c4 * 4 + 0]     = f2tf(rb0.x);
        Bs[buf][k0][c4 * 4 + 1]     = f2tf(rb0.y);
        Bs[buf][k0][c4 * 4 + 2]     = f2tf(rb0.z);
        Bs[buf][k0][c4 * 4 + 3]     = f2tf(rb0.w);
        Bs[buf][k0 + 8][c4 * 4 + 0] = f2tf(rb1.x);
        Bs[buf][k0 + 8][c4 * 4 + 1] = f2tf(rb1.y);
        Bs[buf][k0 + 8][c4 * 4 + 2] = f2tf(rb1.z);
        Bs[buf][k0 + 8][c4 * 4 + 3] = f2tf(rb1.w);
    };

    const int KT = K / BK;
    loadAB(0);
    storeAB(0);
    __syncthreads();

    for (int kt = 0; kt < KT; ++kt) {
        const int buf = kt & 1;
        const bool more = (kt + 1 < KT);
        if (more) loadAB(kt + 1);
#pragma unroll
        for (int kk = 0; kk < 2; ++kk) {
            unsigned af[4][4], bf[4][2];
            const int kb = kk * 8 + tg;
#pragma unroll
            for (int mi = 0; mi < 4; mi++) {
                const int m0 = wm * 64 + mi * 16 + gq;
                af[mi][0] = As[buf][m0][kb];
                af[mi][1] = As[buf][m0 + 8][kb];
                af[mi][2] = As[buf][m0][kb + 4];
                af[mi][3] = As[buf][m0 + 8][kb + 4];
            }
#pragma unroll
            for (int ni = 0; ni < 4; ni++) {
                const int n0 = wn * 32 + ni * 8 + gq;
                bf[ni][0] = Bs[buf][kk * 8 + tg][n0];
                bf[ni][1] = Bs[buf][kk * 8 + tg + 4][n0];
            }
#pragma unroll
            for (int mi = 0; mi < 4; mi++)
#pragma unroll
                for (int ni = 0; ni < 4; ni++)
                    mma_tf32(acc[mi][ni], af[mi], bf[ni]);
        }
        if (more) {
            storeAB(buf ^ 1);
            __syncthreads();
        }
    }

#pragma unroll
    for (int mi = 0; mi < 4; mi++) {
        const int r0 = bm + wm * 64 + mi * 16 + gq;
#pragma unroll
        for (int ni = 0; ni < 4; ni++) {
            const int c0 = bn + wn * 32 + ni * 8 + tg * 2;
            *(float2*)&C[(size_t)r0 * N + c0]       = make_float2(acc[mi][ni][0], acc[mi][ni][1]);
            *(float2*)&C[(size_t)(r0 + 8) * N + c0] = make_float2(acc[mi][ni][2], acc[mi][ni][3]);
        }
    }
}

// ---------------- fused residual add + LayerNorm (in place), batched over z ----------
__global__ void add_ln_kernel(float* __restrict__ x, size_t xzs,
                              const float* __restrict__ r, size_t rzs, int rstride,
                              const float* __restrict__ gamma, const float* __restrict__ beta,
                              size_t gzs)
{
    __shared__ float s1[4], s2[4];
    const int z = blockIdx.y;
    x += (size_t)z * xzs;
    r += (size_t)z * rzs;
    gamma += (size_t)z * gzs;
    beta  += (size_t)z * gzs;
    const int row = blockIdx.x;
    const int t = threadIdx.x;

    float4 xv = *(const float4*)(x + (size_t)row * HD + t * 4);
    float4 rv = *(const float4*)(r + (size_t)row * rstride + t * 4);
    xv.x += rv.x; xv.y += rv.y; xv.z += rv.z; xv.w += rv.w;

    float s = xv.x + xv.y + xv.z + xv.w;
    float q = xv.x * xv.x + xv.y * xv.y + xv.z * xv.z + xv.w * xv.w;
#pragma unroll
    for (int o = 16; o; o >>= 1) {
        s += __shfl_xor_sync(0xffffffffu, s, o);
        q += __shfl_xor_sync(0xffffffffu, q, o);
    }
    if ((t & 31) == 0) { s1[t >> 5] = s; s2[t >> 5] = q; }
    __syncthreads();
    s = s1[0] + s1[1] + s1[2] + s1[3];
    q = s2[0] + s2[1] + s2[2] + s2[3];

    const float mean = s * (1.0f / HD);
    const float var  = q * (1.0f / HD) - mean * mean;
    const float rs   = rsqrtf(var + 1e-5f);

    float4 gv = *(const float4*)(gamma + t * 4);
    float4 bv = *(const float4*)(beta + t * 4);
    float4 ov;
    ov.x = (xv.x - mean) * rs * gv.x + bv.x;
    ov.y = (xv.y - mean) * rs * gv.y + bv.y;
    ov.z = (xv.z - mean) * rs * gv.z + bv.z;
    ov.w = (xv.w - mean) * rs * gv.w + bv.w;
    *(float4*)(x + (size_t)row * HD + t * 4) = ov;
}

// ---------------- folded attention bias: b_att = ao_w @ bv + ao_b ----------------
__global__ void fold_bias_kernel(const float* __restrict__ aow, const float* __restrict__ aob,
                                 const float* __restrict__ qkvb, float* __restrict__ batt)
{
    const int il = blockIdx.x;
    const float* aw = aow + (size_t)il * HD * HD;
    const float* ab = aob + (size_t)il * HD;
    const float* bv = qkvb + ((size_t)il * 3 + 2) * HD;
    const int m = threadIdx.x;
    float sum = ab[m];
    for (int j = 0; j < HD; j++) sum += aw[(size_t)m * HD + j] * bv[j];
    batt[(size_t)il * HD + m] = sum;
}

// ---------------- prior MLP (batch-invariant) ----------------
__global__ void prior_kernel(const float* __restrict__ emb,
                             const float* __restrict__ w1, const float* __restrict__ b1,
                             const float* __restrict__ w2, const float* __restrict__ b2,
                             float* __restrict__ out)
{
    __shared__ float pe[HD];
    __shared__ float ph[2 * HD];
    const int t = threadIdx.x;   // 1024
    if (t < HD) pe[t] = emb[t];
    __syncthreads();
    float s = b1[t];
    for (int k = 0; k < HD; k++) s += pe[k] * w1[(size_t)t * HD + k];
    ph[t] = gelu_f(s);
    __syncthreads();
    float o = b2[t];
    for (int k = 0; k < 2 * HD; k++) o += ph[k] * w2[(size_t)t * 2 * HD + k];
    out[t] = o;
}

// ---------------- final combine ----------------
__global__ void combine_kernel(const float* __restrict__ img, const float* __restrict__ txt,
                               const float* __restrict__ gen_t, const float* __restrict__ gen_i,
                               const float* __restrict__ prior, const float* __restrict__ rw,
                               const int* __restrict__ mt, float* __restrict__ out)
{
    const int idx = blockIdx.x * blockDim.x + threadIdx.x;
    if (idx >= BATCH * HD) return;
    const int b = idx >> 9;
    const int j = idx & (HD - 1);
    const int m = mt[b];
    const float iv = img[idx], tv = txt[idx];
    const float r0 = rw[0], r1 = rw[1];
    const float gt = r0 * tv + (1.0f - r0) * gen_t[idx];
    const float gi = r1 * iv + (1.0f - r1) * gen_i[idx];
    const float ei = (m == 3) ? prior[j]      : ((m == 2) ? gi : iv);
    const float et = (m == 3) ? prior[HD + j] : ((m == 1) ? gt : tv);
    out[idx] = ei;
    out[(size_t)BATCH * HD + idx] = et;
}

// ---------------- launch ----------------
extern "C" void kernel_launch(void* const* d_in, const int* in_sizes, int n_in,
                              void* d_out, int out_size)
{
    const float* image = (const float*)d_in[0];
    const float* text  = (const float*)d_in[1];
    const float* ipw   = (const float*)d_in[2];
    const float* ipb   = (const float*)d_in[3];
    const float* qkvw  = (const float*)d_in[4];
    const float* qkvb  = (const float*)d_in[5];
    const float* aow   = (const float*)d_in[6];
    const float* aob   = (const float*)d_in[7];
    const float* ln1g  = (const float*)d_in[8];
    const float* ln1b  = (const float*)d_in[9];
    const float* ln2g  = (const float*)d_in[10];
    const float* ln2b  = (const float*)d_in[11];
    const float* f1w   = (const float*)d_in[12];
    const float* f1b   = (const float*)d_in[13];
    const float* f2w   = (const float*)d_in[14];
    const float* f2b   = (const float*)d_in[15];
    const float* opw   = (const float*)d_in[16];
    const float* opb   = (const float*)d_in[17];
    const float* rw    = (const float*)d_in[18];
    const float* pw1   = (const float*)d_in[19];
    const float* pb1   = (const float*)d_in[20];
    const float* pw2   = (const float*)d_in[21];
    const float* pb2   = (const float*)d_in[22];
    const float* pemb  = (const float*)d_in[23];
    const int*   mt    = (const int*)d_in[24];
    float* out = (float*)d_out;

    float *Watt, *batt, *ATT, *X, *Hb, *T, *G, *PR;
    cudaGetSymbolAddress((void**)&Watt, g_Watt);
    cudaGetSymbolAddress((void**)&batt, g_batt);
    cudaGetSymbolAddress((void**)&ATT,  g_ATT);
    cudaGetSymbolAddress((void**)&X,    g_X);
    cudaGetSymbolAddress((void**)&Hb,   g_Hb);
    cudaGetSymbolAddress((void**)&T,    g_T);
    cudaGetSymbolAddress((void**)&G,    g_G);
    cudaGetSymbolAddress((void**)&PR,   g_prior);

    const int SMEMSZ = 4 * (128 + 128) * 20 * 4;   // 81920 B per CTA, 2 CTAs/SM
    cudaFuncSetAttribute(gemm2_kernel<false>, cudaFuncAttributeMaxDynamicSharedMemorySize, SMEMSZ);
    cudaFuncSetAttribute(gemm2_kernel<true>,  cudaFuncAttributeMaxDynamicSharedMemorySize, SMEMSZ);

    const size_t BH  = (size_t)BATCH * HD;
    const size_t BF  = (size_t)BATCH * FF;
    const size_t B3H = (size_t)BATCH * 3 * HD;

    // 1) fold weights + biases + prior (tiny, front of the graph)
    fold_gemm_kernel<<<dim3(4, 4, 6), 256>>>(aow, qkvw, Watt);
    fold_bias_kernel<<<6, HD>>>(aow, aob, qkvb, batt);
    prior_kernel<<<1, 1024>>>(pemb, pw1, pb1, pw2, pb2, PR);

    // 2) all-layer attention adds, both gens: ATT[z] = tgt_z @ Watt_z.T + batt_z
    gemm2_kernel<false><<<dim3(3 * HD / 128, BATCH / 128, 2), 128, SMEMSZ>>>(
        text, image, 0, Watt, (size_t)3 * HD * HD, batt, (size_t)3 * HD,
        ATT, B3H, BATCH, 3 * HD, HD);

    // 3) input projection, both gens: X[z] = src_z @ ipw_z.T + ipb_z
    gemm2_kernel<false><<<dim3(HD / 128, BATCH / 128, 2), 128, SMEMSZ>>>(
        image, text, 0, ipw, (size_t)HD * HD, ipb, HD,
        X, BH, BATCH, HD, HD);

    for (int l = 0; l < NLAYER; l++) {
        // x = LN(x + attn_l)
        add_ln_kernel<<<dim3(BATCH, 2), 128>>>(
            X, BH, ATT + (size_t)l * HD, B3H, 3 * HD,
            ln1g + (size_t)l * HD, ln1b + (size_t)l * HD, (size_t)NLAYER * HD);
        // h = gelu(x @ f1w.T + f1b)
        gemm2_kernel<true><<<dim3(FF / 128, BATCH / 128, 2), 128, SMEMSZ>>>(
            X, X, BH, f1w + (size_t)l * FF * HD, (size_t)NLAYER * FF * HD,
            f1b + (size_t)l * FF, (size_t)NLAYER * FF,
            Hb, BF, BATCH, FF, HD);
        // t = h @ f2w.T + f2b
        gemm2_kernel<false><<<dim3(HD / 128, BATCH / 128, 2), 128, SMEMSZ>>>(
            Hb, Hb, BF, f2w + (size_t)l * HD * FF, (size_t)NLAYER * HD * FF,
            f2b + (size_t)l * HD, (size_t)NLAYER * HD,
            T, BH, BATCH, HD, FF);
        // x = LN(x + t)
        add_ln_kernel<<<dim3(BATCH, 2), 128>>>(
            X, BH, T, BH, HD,
            ln2g + (size_t)l * HD, ln2b + (size_t)l * HD, (size_t)NLAYER * HD);
    }

    // 4) output projection, both gens
    gemm2_kernel<false><<<dim3(HD / 128, BATCH / 128, 2), 128, SMEMSZ>>>(
        X, X, BH, opw, (size_t)HD * HD, opb, HD,
        G, BH, BATCH, HD, HD);

    // 5) final mix + missing_type selection
    combine_kernel<<<(BATCH * HD + 255) / 256, 256>>>(image, text, G, G + BH, PR, rw, mt, out);
}